// round 12
// baseline (speedup 1.0000x reference)
#include <cuda_runtime.h>
#include <stdint.h>

// SeqOperation_28106265985064 — persistent grid-stride variant (last lever).
//
// Collapsed gather, p = pos_idx[b] (int32 on device):
//   out[b,i,:] = seq[b,p,:]     if i == (p+1) % n          (ungated)
//              = seq[b,i,:]     if p<=n-3 && i < p
//              = seq[b,i-2,:]   if p<=n-3 && i >= p+3
//              = 0              otherwise
// seq: (B=4096, n=200, d=128) f32. ~830 MB minimal traffic.
//
// History: R3 145.8us (MLP=1) -> R5 123.4us (MLP=2, 83% DRAM) -> R6/R9/R10/R11
// all flat (MLP=4, streaming hints, 512t blocks). Pinned at ~6.6 TB/s HBM R/W.
// This round: single-wave persistent launch (grid = 148*8) to remove the ~43
// wave transitions + CTA launch overhead; loop allows SW pipelining of loads.

constexpr int N_SEQ = 200;
constexpr int D4    = 32;            // d=128 floats = 32 float4 per row
constexpr int ROWS_PER_WARP   = 2;   // per loop iteration
constexpr int WARPS_PER_BLOCK = 8;   // 256 threads
constexpr int NUM_SMS         = 148;
constexpr int BLOCKS_PER_SM   = 8;
constexpr int GRID_BLOCKS     = NUM_SMS * BLOCKS_PER_SM;  // 1184

__device__ __forceinline__ int src_row(int i, int p)
{
    // source row within batch, or -1 for zero-fill
    bool valid = (p <= N_SEQ - 3);
    int pp1 = (p + 1 == N_SEQ) ? 0 : (p + 1);
    if (i == pp1) return p;                    // rolled "pos" term, NOT gated
    if (valid) {
        if (i < p)      return i;              // left term
        if (i >= p + 3) return i - 2;          // rolled "right" term
    }
    return -1;
}

__global__ __launch_bounds__(256)
void seqop_kernel(const float4* __restrict__ seq,
                  const int* __restrict__ pos_idx,
                  float4* __restrict__ out,
                  int total_rows)
{
    int warp   = blockIdx.x * WARPS_PER_BLOCK + (threadIdx.x >> 5);
    int lane   = threadIdx.x & 31;
    int nwarps = GRID_BLOCKS * WARPS_PER_BLOCK;           // 9472
    int stride = nwarps * ROWS_PER_WARP;                  // rows per sweep

    for (int r0 = warp * ROWS_PER_WARP; r0 < total_rows; r0 += stride) {
        int src[ROWS_PER_WARP];

        #pragma unroll
        for (int k = 0; k < ROWS_PER_WARP; k++) {
            int r = r0 + k;                               // r < total_rows:
            int b = r / N_SEQ;                            // total_rows even,
            int i = r - b * N_SEQ;                        // stride even
            int p = __ldg(&pos_idx[b]);
            src[k] = src_row(i, p);
            if (src[k] >= 0) src[k] += b * N_SEQ;         // absolute row
        }

        // Front-batch loads: both LDG.128 in flight (MLP>=2; loop overlap
        // lets the next iteration's loads issue behind these stores).
        float4 v[ROWS_PER_WARP];
        #pragma unroll
        for (int k = 0; k < ROWS_PER_WARP; k++) {
            v[k] = make_float4(0.f, 0.f, 0.f, 0.f);
            if (src[k] >= 0)
                v[k] = __ldg(&seq[src[k] * D4 + lane]);
        }

        #pragma unroll
        for (int k = 0; k < ROWS_PER_WARP; k++) {
            out[(r0 + k) * D4 + lane] = v[k];             // d_out poisoned
        }
    }
}

extern "C" void kernel_launch(void* const* d_in, const int* in_sizes, int n_in,
                              void* d_out, int out_size)
{
    const float4* seq = (const float4*)d_in[0];
    const int*    pos = (const int*)d_in[1];
    float4*       o   = (float4*)d_out;

    int B = in_sizes[1];                 // 4096
    int total_rows = B * N_SEQ;          // 819200 (even; stride is even too,
                                         // so r0+1 never crosses total_rows)

    seqop_kernel<<<GRID_BLOCKS, 256>>>(seq, pos, o, total_rows);
}

// round 13
// speedup vs baseline: 1.1013x; 1.1013x over previous
#include <cuda_runtime.h>
#include <stdint.h>

// SeqOperation_28106265985064 — FINAL (reverted to verified-best R5/R11 config
// after R12 persistent-grid regression).
//
// Algebraic collapse of the reference (one-hot/roll/where chain) into a
// per-row gather, p = pos_idx[b] (int32 on device):
//   out[b,i,:] = seq[b,p,:]     if i == (p+1) % n          (ungated)
//              = seq[b,i,:]     if p<=n-3 && i < p
//              = seq[b,i-2,:]   if p<=n-3 && i >= p+3
//              = 0              otherwise
// seq: (B=4096, n=200, d=128) f32. ~830 MB minimal traffic (read once + write).
//
// Session evidence:
//   R3  warp/row, MLP=1           : 145.8us @ 69.8% DRAM (latency-exposed)
//   R5  2 rows/warp, MLP=2        : 123.4us @ 83.2% DRAM  <- WIN
//   R6  MLP=4                     : flat   (latency lever saturated)
//   R9  __ldcs/__stcs             : flat   (cache policy non-binding)
//   R10 512-thread blocks         : flat   (occupancy non-binding)
//   R12 persistent grid-stride    : 135.6us REGRESSION (loop-carried dep kills
//        free cross-CTA MLP; strided sweep hurts DRAM locality)
// Conclusion: flat launch, 2 rows/warp, default cache policy is optimal;
// pinned at ~6.6 TB/s achieved HBM mixed-R/W ceiling (~83% of spec).

constexpr int N_SEQ = 200;
constexpr int D4    = 32;            // d=128 floats = 32 float4 per row
constexpr int ROWS_PER_WARP   = 2;
constexpr int WARPS_PER_BLOCK = 8;   // 256 threads
constexpr int ROWS_PER_BLOCK  = ROWS_PER_WARP * WARPS_PER_BLOCK;  // 16

__device__ __forceinline__ int src_row(int i, int p)
{
    // source row within batch, or -1 for zero-fill
    bool valid = (p <= N_SEQ - 3);
    int pp1 = (p + 1 == N_SEQ) ? 0 : (p + 1);
    if (i == pp1) return p;                    // rolled "pos" term, NOT gated
    if (valid) {
        if (i < p)      return i;              // left term
        if (i >= p + 3) return i - 2;          // rolled "right" term
    }
    return -1;
}

__global__ __launch_bounds__(256)
void seqop_kernel(const float4* __restrict__ seq,
                  const int* __restrict__ pos_idx,
                  float4* __restrict__ out,
                  int total_rows)
{
    int warp = blockIdx.x * WARPS_PER_BLOCK + (threadIdx.x >> 5);
    int lane = threadIdx.x & 31;
    int r0   = warp * ROWS_PER_WARP;
    if (r0 >= total_rows) return;

    int src[ROWS_PER_WARP];

    #pragma unroll
    for (int k = 0; k < ROWS_PER_WARP; k++) {
        int r = r0 + k;
        int b = r / N_SEQ;
        int i = r - b * N_SEQ;
        int p = __ldg(&pos_idx[b]);
        src[k] = src_row(i, p);
        if (src[k] >= 0) src[k] += b * N_SEQ;  // absolute source row
    }

    // Front-batch loads so both LDG.128 are concurrently in flight (MLP=2):
    // the change that took DRAM from 69.8% to 83.2% of peak.
    float4 v[ROWS_PER_WARP];
    #pragma unroll
    for (int k = 0; k < ROWS_PER_WARP; k++) {
        v[k] = make_float4(0.f, 0.f, 0.f, 0.f);
        if (src[k] >= 0)
            v[k] = __ldg(&seq[src[k] * D4 + lane]);
    }

    #pragma unroll
    for (int k = 0; k < ROWS_PER_WARP; k++) {
        out[(r0 + k) * D4 + lane] = v[k];      // always write: d_out poisoned
    }
}

extern "C" void kernel_launch(void* const* d_in, const int* in_sizes, int n_in,
                              void* d_out, int out_size)
{
    const float4* seq = (const float4*)d_in[0];
    const int*    pos = (const int*)d_in[1];
    float4*       o   = (float4*)d_out;

    int B = in_sizes[1];                 // 4096
    int total_rows = B * N_SEQ;          // 819200

    int grid = (total_rows + ROWS_PER_BLOCK - 1) / ROWS_PER_BLOCK;  // 51200
    seqop_kernel<<<grid, 256>>>(seq, pos, o, total_rows);
}

// round 14
// speedup vs baseline: 1.1019x; 1.0005x over previous
#include <cuda_runtime.h>
#include <stdint.h>

// SeqOperation_28106265985064 — FINAL, converged.
//
// Algebraic collapse of the reference (one-hot/roll/where chain) into a
// per-row gather, p = pos_idx[b] (int32 on device):
//   out[b,i,:] = seq[b,p,:]     if i == (p+1) % n          (ungated)
//              = seq[b,i,:]     if p<=n-3 && i < p
//              = seq[b,i-2,:]   if p<=n-3 && i >= p+3
//              = 0              otherwise
// seq: (B=4096, n=200, d=128) f32. ~830 MB minimal traffic (read once + write).
//
// Session evidence (all levers measured):
//   R3  warp/row, MLP=1           : 145.8us @ 69.8% DRAM (latency-exposed)
//   R5  2 rows/warp, MLP=2        : 123.4us @ 83.2% DRAM  <- WIN
//   R6  MLP=4                     : flat   (latency fully hidden at MLP=2)
//   R9  __ldcs/__stcs             : flat   (cache policy non-binding)
//   R10 512-thread blocks         : flat   (occupancy non-binding)
//   R12 persistent grid-stride    : 135.6us REGRESSION (flat launch's free
//        cross-CTA MLP + dense locality beats a loop-carried sweep)
//   R13 re-confirm                : 123.2us @ 83.8% DRAM, 6.64 TB/s
// Pinned at the achieved HBM mixed-R/W ceiling; traffic at logical minimum;
// LTS cap is path-independent on B300 so TMA/cp.async offer nothing.

constexpr int N_SEQ = 200;
constexpr int D4    = 32;            // d=128 floats = 32 float4 per row
constexpr int ROWS_PER_WARP   = 2;
constexpr int WARPS_PER_BLOCK = 8;   // 256 threads
constexpr int ROWS_PER_BLOCK  = ROWS_PER_WARP * WARPS_PER_BLOCK;  // 16

__device__ __forceinline__ int src_row(int i, int p)
{
    // source row within batch, or -1 for zero-fill
    bool valid = (p <= N_SEQ - 3);
    int pp1 = (p + 1 == N_SEQ) ? 0 : (p + 1);
    if (i == pp1) return p;                    // rolled "pos" term, NOT gated
    if (valid) {
        if (i < p)      return i;              // left term
        if (i >= p + 3) return i - 2;          // rolled "right" term
    }
    return -1;
}

__global__ __launch_bounds__(256)
void seqop_kernel(const float4* __restrict__ seq,
                  const int* __restrict__ pos_idx,
                  float4* __restrict__ out,
                  int total_rows)
{
    int warp = blockIdx.x * WARPS_PER_BLOCK + (threadIdx.x >> 5);
    int lane = threadIdx.x & 31;
    int r0   = warp * ROWS_PER_WARP;
    if (r0 >= total_rows) return;

    int src[ROWS_PER_WARP];

    #pragma unroll
    for (int k = 0; k < ROWS_PER_WARP; k++) {
        int r = r0 + k;
        int b = r / N_SEQ;
        int i = r - b * N_SEQ;
        int p = __ldg(&pos_idx[b]);
        src[k] = src_row(i, p);
        if (src[k] >= 0) src[k] += b * N_SEQ;  // absolute source row
    }

    // Front-batch loads so both LDG.128 are concurrently in flight (MLP=2):
    // the change that took DRAM from 69.8% to 83+% of peak.
    float4 v[ROWS_PER_WARP];
    #pragma unroll
    for (int k = 0; k < ROWS_PER_WARP; k++) {
        v[k] = make_float4(0.f, 0.f, 0.f, 0.f);
        if (src[k] >= 0)
            v[k] = __ldg(&seq[src[k] * D4 + lane]);
    }

    #pragma unroll
    for (int k = 0; k < ROWS_PER_WARP; k++) {
        out[(r0 + k) * D4 + lane] = v[k];      // always write: d_out poisoned
    }
}

extern "C" void kernel_launch(void* const* d_in, const int* in_sizes, int n_in,
                              void* d_out, int out_size)
{
    const float4* seq = (const float4*)d_in[0];
    const int*    pos = (const int*)d_in[1];
    float4*       o   = (float4*)d_out;

    int B = in_sizes[1];                 // 4096
    int total_rows = B * N_SEQ;          // 819200

    int grid = (total_rows + ROWS_PER_BLOCK - 1) / ROWS_PER_BLOCK;  // 51200
    seqop_kernel<<<grid, 256>>>(seq, pos, o, total_rows);
}

// round 15
// speedup vs baseline: 1.1030x; 1.0010x over previous
#include <cuda_runtime.h>
#include <stdint.h>

// SeqOperation_28106265985064 — FINAL, converged (4x reproduced: 123.4/123.3/
// 123.2/123.1 us @ ~83% DRAM, 6.6 TB/s).
//
// Algebraic collapse of the reference (one-hot/roll/where chain) into a
// per-row gather, p = pos_idx[b] (int32 on device):
//   out[b,i,:] = seq[b,p,:]     if i == (p+1) % n          (ungated)
//              = seq[b,i,:]     if p<=n-3 && i < p
//              = seq[b,i-2,:]   if p<=n-3 && i >= p+3
//              = 0              otherwise
// seq: (B=4096, n=200, d=128) f32. ~830 MB minimal traffic (read once + write).
//
// Lever matrix (all measured, session R3-R14):
//   MLP 1->2 front-batched loads : WIN  145.8 -> 123.4us, DRAM 69.8 -> 83.2%
//   MLP 2->4                     : flat (latency fully hidden at MLP=2)
//   __ldcs/__stcs streaming      : flat (cache policy non-binding)
//   512-thread blocks            : flat (occupancy non-binding)
//   persistent grid-stride       : REGRESSION +10% (flat launch's cross-CTA
//                                  MLP + dense per-wave locality wins)
// Closed channels: traffic at logical floor; LTS cap path-independent on B300
// (TMA == LDG); no SM-side constraint (issue 24%, pipes <18%). This is the
// achieved HBM mixed-R/W roofline for this access pattern.

constexpr int N_SEQ = 200;
constexpr int D4    = 32;            // d=128 floats = 32 float4 per row
constexpr int ROWS_PER_WARP   = 2;
constexpr int WARPS_PER_BLOCK = 8;   // 256 threads
constexpr int ROWS_PER_BLOCK  = ROWS_PER_WARP * WARPS_PER_BLOCK;  // 16

__device__ __forceinline__ int src_row(int i, int p)
{
    // source row within batch, or -1 for zero-fill
    bool valid = (p <= N_SEQ - 3);
    int pp1 = (p + 1 == N_SEQ) ? 0 : (p + 1);
    if (i == pp1) return p;                    // rolled "pos" term, NOT gated
    if (valid) {
        if (i < p)      return i;              // left term
        if (i >= p + 3) return i - 2;          // rolled "right" term
    }
    return -1;
}

__global__ __launch_bounds__(256)
void seqop_kernel(const float4* __restrict__ seq,
                  const int* __restrict__ pos_idx,
                  float4* __restrict__ out,
                  int total_rows)
{
    int warp = blockIdx.x * WARPS_PER_BLOCK + (threadIdx.x >> 5);
    int lane = threadIdx.x & 31;
    int r0   = warp * ROWS_PER_WARP;
    if (r0 >= total_rows) return;

    int src[ROWS_PER_WARP];

    #pragma unroll
    for (int k = 0; k < ROWS_PER_WARP; k++) {
        int r = r0 + k;
        int b = r / N_SEQ;
        int i = r - b * N_SEQ;
        int p = __ldg(&pos_idx[b]);
        src[k] = src_row(i, p);
        if (src[k] >= 0) src[k] += b * N_SEQ;  // absolute source row
    }

    // Front-batch loads so both LDG.128 are concurrently in flight (MLP=2).
    float4 v[ROWS_PER_WARP];
    #pragma unroll
    for (int k = 0; k < ROWS_PER_WARP; k++) {
        v[k] = make_float4(0.f, 0.f, 0.f, 0.f);
        if (src[k] >= 0)
            v[k] = __ldg(&seq[src[k] * D4 + lane]);
    }

    #pragma unroll
    for (int k = 0; k < ROWS_PER_WARP; k++) {
        out[(r0 + k) * D4 + lane] = v[k];      // always write: d_out poisoned
    }
}

extern "C" void kernel_launch(void* const* d_in, const int* in_sizes, int n_in,
                              void* d_out, int out_size)
{
    const float4* seq = (const float4*)d_in[0];
    const int*    pos = (const int*)d_in[1];
    float4*       o   = (float4*)d_out;

    int B = in_sizes[1];                 // 4096
    int total_rows = B * N_SEQ;          // 819200

    int grid = (total_rows + ROWS_PER_BLOCK - 1) / ROWS_PER_BLOCK;  // 51200
    seqop_kernel<<<grid, 256>>>(seq, pos, o, total_rows);
}